// round 1
// baseline (speedup 1.0000x reference)
#include <cuda_runtime.h>
#include <math.h>
#include <stdint.h>

#define NIMG 8
#define CIN 256
#define HH 64
#define WW 64
#define HW 4096
#define NA 9
#define APIMG 36864      // HW * NA
#define NPRE 6000
#define NPOST 300
#define KDIM 2304        // 256 * 9
#define NWORDS 94        // ceil(6000/64)

#define OFF_LOC   0
#define OFF_SCORE 1179648
#define OFF_ROIS  1769472
#define OFF_RIDX  1779072
#define OFF_ANCH  1781472

// ---------------- static device scratch (no allocations allowed) ----------------
__device__ float g_wT[KDIM * 256];                              // 2.36 MB  weights k-major
__device__ float g_h[NIMG * CIN * HW];                          // 33.5 MB  conv1 output
__device__ float g_boxes[NIMG * APIMG * 4];                     // 4.7 MB   decoded+clipped boxes
__device__ unsigned g_key[NIMG * APIMG];                        // 1.18 MB  ascending sort key (desc score)
__device__ float g_top[NIMG * NPRE * 4];                        // 0.77 MB  top-6000 boxes, sorted
__device__ unsigned long long g_mask[(size_t)NIMG * NPRE * NWORDS]; // 36 MB NMS bitmask

// ---------------- helpers ----------------
__device__ __forceinline__ float read_dim(const void* p) {
    int v = *(const int*)p;
    if (v > 0 && v < 1048576) return (float)v;
    long long l = *(const long long*)p;
    if (l > 0 && l < 1048576) return (float)l;
    return *(const float*)p;
}

// ---------------- K0: transpose conv1 weights to k-major (k = tap*256 + c) ----------------
__global__ void k_wt(const float* __restrict__ w) {
    int o = blockIdx.x;  // 0..255
    for (int k = threadIdx.x; k < KDIM; k += 256) {
        int c = k & 255;
        int tap = k >> 8;  // ky*3+kx
        g_wT[(size_t)k * 256 + o] = w[(size_t)o * KDIM + c * 9 + tap];
    }
}

// ---------------- K1: conv3x3 SAME + bias + relu, implicit im2col SGEMM ----------------
// M = 32768 pixels (n,y,x), N = 256 out channels, K = 2304.
// Block: 256 threads, 128x128 C tile, BK=8, 8x8 micro-tile per thread.
__global__ void __launch_bounds__(256) k_conv(const float* __restrict__ x,
                                              const float* __restrict__ bias) {
    __shared__ __align__(16) float As[8][128];
    __shared__ __align__(16) float Bs[8][128];
    const int m0 = blockIdx.x * 128;
    const int n0 = blockIdx.y * 128;
    const int tx = threadIdx.x & 15, ty = threadIdx.x >> 4;
    float acc[8][8];
#pragma unroll
    for (int i = 0; i < 8; i++)
#pragma unroll
        for (int j = 0; j < 8; j++) acc[i][j] = 0.f;

    for (int k0 = 0; k0 < KDIM; k0 += 8) {
#pragma unroll
        for (int t = 0; t < 4; t++) {
            int idx = threadIdx.x + t * 256;
            int kk = idx >> 7;
            int l = idx & 127;
            // A tile: im2col gather
            {
                int m = m0 + l;
                int n = m >> 12;
                int p = m & 4095;
                int yy = p >> 6, xx = p & 63;
                int k = k0 + kk;
                int tap = k >> 8;
                int c = k & 255;
                int ky = tap / 3;
                int kx = tap - ky * 3;
                int y2 = yy + ky - 1, x2 = xx + kx - 1;
                float v = 0.f;
                if ((unsigned)y2 < 64u && (unsigned)x2 < 64u)
                    v = x[(((size_t)n * CIN + c) << 12) + (y2 << 6) + x2];
                As[kk][l] = v;
            }
            // B tile: k-major weights, coalesced
            Bs[kk][l] = g_wT[(size_t)(k0 + kk) * 256 + n0 + l];
        }
        __syncthreads();
#pragma unroll
        for (int kk = 0; kk < 8; kk++) {
            float4 a0 = ((const float4*)As[kk])[ty * 2];
            float4 a1 = ((const float4*)As[kk])[ty * 2 + 1];
            float4 b0 = ((const float4*)Bs[kk])[tx * 2];
            float4 b1 = ((const float4*)Bs[kk])[tx * 2 + 1];
            float av[8] = {a0.x, a0.y, a0.z, a0.w, a1.x, a1.y, a1.z, a1.w};
            float bv[8] = {b0.x, b0.y, b0.z, b0.w, b1.x, b1.y, b1.z, b1.w};
#pragma unroll
            for (int i2 = 0; i2 < 8; i2++)
#pragma unroll
                for (int j2 = 0; j2 < 8; j2++) acc[i2][j2] += av[i2] * bv[j2];
        }
        __syncthreads();
    }
#pragma unroll
    for (int i = 0; i < 8; i++) {
        int m = m0 + ty * 8 + i;
        int n = m >> 12;
        int p = m & 4095;
#pragma unroll
        for (int j = 0; j < 8; j++) {
            int o = n0 + tx * 8 + j;
            g_h[(((size_t)n * CIN + o) << 12) + p] = fmaxf(acc[i][j] + bias[o], 0.f);
        }
    }
}

// ---------------- K2: fused 1x1 heads + softmax-fg + decode/clip/valid + keys ----------------
// One block = 4 pixels, 256 threads.
__global__ void __launch_bounds__(256) k_heads(const float* __restrict__ lw,
                                               const float* __restrict__ lb,
                                               const float* __restrict__ sw,
                                               const float* __restrict__ sb,
                                               float* __restrict__ out,
                                               const void* pih, const void* piw) {
    __shared__ float sh[4][256];
    __shared__ float so[4][56];
    int p0 = blockIdx.x * 4;
    int n = p0 >> 12;
    int pbase = p0 & 4095;
    for (int idx = threadIdx.x; idx < 1024; idx += 256) {
        int px = idx & 3;
        int c = idx >> 2;
        sh[px][c] = g_h[(((size_t)n * CIN + c) << 12) + pbase + px];
    }
    __syncthreads();
    {
        int px = threadIdx.x >> 6;
        int ch = threadIdx.x & 63;
        if (ch < 54) {
            const float* wv;
            float bv;
            if (ch < 36) { wv = lw + (size_t)ch * 256; bv = lb[ch]; }
            else         { wv = sw + (size_t)(ch - 36) * 256; bv = sb[ch - 36]; }
            float acc = 0.f;
#pragma unroll 8
            for (int k = 0; k < 256; k++) acc += sh[px][k] * wv[k];
            acc += bv;
            so[px][ch] = acc;
            int pp = (p0 + px) & 4095;
            if (ch < 36)
                out[OFF_LOC + (size_t)n * 147456 + (size_t)pp * 36 + ch] = acc;
            else
                out[OFF_SCORE + (size_t)n * 73728 + (size_t)pp * 18 + (ch - 36)] = acc;
        }
    }
    __syncthreads();
    if (threadIdx.x < 36) {
        int px = threadIdx.x / 9;
        int a = threadIdx.x % 9;
        int pp = (p0 + px) & 4095;
        int y = pp >> 6, xq = pp & 63;
        const double RAT[3] = {0.5, 1.0, 2.0};
        const double SCL[3] = {8.0, 16.0, 32.0};
        int ri = a / 3, sj = a % 3;
        double hh = 7.0 * SCL[sj] * sqrt(RAT[ri]);
        double wd = 7.0 * SCL[sj] * sqrt(1.0 / RAT[ri]);
        float ab0 = (float)(3.5 - hh / 2.0), ab1 = (float)(3.5 - wd / 2.0);
        float ab2 = (float)(3.5 + hh / 2.0), ab3 = (float)(3.5 + wd / 2.0);
        float shy = (float)(y * 16), shx = (float)(xq * 16);
        float A0 = shy + ab0, A1 = shx + ab1, A2 = shy + ab2, A3 = shx + ab3;
        long aidx = (long)pp * NA + a;
        if (n == 0) {
            float* ao = out + OFF_ANCH + (size_t)aidx * 4;
            ao[0] = A0; ao[1] = A1; ao[2] = A2; ao[3] = A3;
        }
        float ah = A2 - A0, aw = A3 - A1;
        float acy = A0 + 0.5f * ah, acx = A1 + 0.5f * aw;
        float dy = so[px][a * 4 + 0], dx = so[px][a * 4 + 1];
        float dh = so[px][a * 4 + 2], dw = so[px][a * 4 + 3];
        float cy = dy * ah + acy;
        float cx = dx * aw + acx;
        float bh = expf(dh) * ah;
        float bw = expf(dw) * aw;
        float imh = read_dim(pih), imw = read_dim(piw);
        float y1 = fminf(fmaxf(cy - 0.5f * bh, 0.f), imh);
        float x1 = fminf(fmaxf(cx - 0.5f * bw, 0.f), imw);
        float y2 = fminf(fmaxf(cy + 0.5f * bh, 0.f), imh);
        float x2 = fminf(fmaxf(cx + 0.5f * bw, 0.f), imw);
        bool valid = ((y2 - y1) >= 16.f) && ((x2 - x1) >= 16.f);
        float s0 = so[px][36 + 2 * a], s1 = so[px][37 + 2 * a];
        float m = fmaxf(s0, s1);
        float e0 = expf(s0 - m), e1 = expf(s1 - m);
        float fg = __fdiv_rn(e1, __fadd_rn(e0, e1));
        float sc = valid ? fg : -INFINITY;
        unsigned u = __float_as_uint(sc);
        unsigned sbits = (u & 0x80000000u) ? ~u : (u | 0x80000000u);  // ascending-sortable
        size_t gi = (size_t)n * APIMG + aidx;
        g_key[gi] = ~sbits;  // ascending key == descending score
        float* bp = g_boxes + gi * 4;
        bp[0] = y1; bp[1] = x1; bp[2] = y2; bp[3] = x2;
    }
}

// ---------------- K3: exact top-6000 per image (radix select + bitonic sort) --------------
// One block per image, 1024 threads. Dyn smem: keys[36864] u32 + buf[8192] u64 = 212992 B.
__global__ void __launch_bounds__(1024) k_topk() {
    extern __shared__ unsigned smem[];
    unsigned* keys = smem;
    unsigned long long* buf = (unsigned long long*)(smem + APIMG);
    __shared__ int hist[256];
    __shared__ unsigned s_val;
    __shared__ int s_rem;
    __shared__ int s_cnt;
    int n = blockIdx.x;
    int tid = threadIdx.x;
    const unsigned* gk = g_key + (size_t)n * APIMG;
    for (int i = tid; i < APIMG; i += 1024) keys[i] = gk[i];
    __syncthreads();

    // radix select: value of the 6000-th smallest key
    unsigned prefix = 0, mask = 0;
    int rem = NPRE;
    for (int pass = 0; pass < 4; pass++) {
        int shift = 24 - pass * 8;
        if (tid < 256) hist[tid] = 0;
        __syncthreads();
        for (int i = tid; i < APIMG; i += 1024) {
            unsigned k = keys[i];
            if ((k & mask) == prefix) atomicAdd(&hist[(k >> shift) & 255], 1);
        }
        __syncthreads();
        if (tid == 0) {
            int accu = 0;
            for (int d = 0; d < 256; d++) {
                int c = hist[d];
                if (accu + c >= rem) { s_val = prefix | ((unsigned)d << shift); s_rem = rem - accu; break; }
                accu += c;
            }
        }
        __syncthreads();
        prefix = s_val;
        rem = s_rem;
        mask |= (0xFFu << shift);
    }
    unsigned T = prefix;
    int r = rem;  // need r elements ==T with smallest indices

    // tie-break: r-th smallest index among keys==T (indices < 2^16)
    unsigned ipref = 0, im = 0;
    int ir = r;
    for (int pass = 0; pass < 2; pass++) {
        int shift = 8 - pass * 8;
        if (tid < 256) hist[tid] = 0;
        __syncthreads();
        for (int i = tid; i < APIMG; i += 1024) {
            if (keys[i] == T && (((unsigned)i & im) == ipref))
                atomicAdd(&hist[((unsigned)i >> shift) & 255], 1);
        }
        __syncthreads();
        if (tid == 0) {
            int accu = 0;
            for (int d = 0; d < 256; d++) {
                int c = hist[d];
                if (accu + c >= ir) { s_val = ipref | ((unsigned)d << shift); s_rem = ir - accu; break; }
                accu += c;
            }
        }
        __syncthreads();
        ipref = s_val;
        ir = s_rem;
        im |= (0xFFu << shift);
    }
    unsigned idxT = ipref;

    // compact exactly 6000 survivors (unordered), then bitonic-sort 8192 u64 keys
    if (tid == 0) s_cnt = 0;
    __syncthreads();
    for (int i = tid; i < APIMG; i += 1024) {
        unsigned k = keys[i];
        if (k < T || (k == T && (unsigned)i <= idxT)) {
            int pos = atomicAdd(&s_cnt, 1);
            buf[pos] = (((unsigned long long)k) << 32) | (unsigned)i;
        }
    }
    __syncthreads();
    int cnt = s_cnt;
    for (int i = tid; i < 8192; i += 1024)
        if (i >= cnt) buf[i] = 0xFFFFFFFFFFFFFFFFull;
    __syncthreads();
    for (int size = 2; size <= 8192; size <<= 1) {
        for (int stride = size >> 1; stride > 0; stride >>= 1) {
            for (int i = tid; i < 8192; i += 1024) {
                int ixj = i ^ stride;
                if (ixj > i) {
                    bool up = ((i & size) == 0);
                    unsigned long long va = buf[i], vb = buf[ixj];
                    if ((va > vb) == up) { buf[i] = vb; buf[ixj] = va; }
                }
            }
            __syncthreads();
        }
    }
    // gather top boxes in rank order
    for (int r2 = tid; r2 < NPRE; r2 += 1024) {
        unsigned idx = (unsigned)(buf[r2] & 0xFFFFFFFFull);
        float4 bb = *(const float4*)(g_boxes + ((size_t)n * APIMG + idx) * 4);
        *(float4*)(g_top + ((size_t)n * NPRE + r2) * 4) = bb;
    }
}

// ---------------- K4: NMS bitmask matrix ----------------
__global__ void __launch_bounds__(64) k_mask() {
    int n = blockIdx.z;
    int it = blockIdx.x, jt = blockIdx.y;
    __shared__ float4 sb[64];
    __shared__ float sarea[64];
    int tid = threadIdx.x;
    int j = jt * 64 + tid;
    float4 bj = (j < NPRE) ? *(const float4*)(g_top + ((size_t)n * NPRE + j) * 4)
                           : make_float4(0, 0, 0, 0);
    sb[tid] = bj;
    sarea[tid] = (bj.z - bj.x) * (bj.w - bj.y);
    __syncthreads();
    int i = it * 64 + tid;
    if (i >= NPRE) return;
    float4 bi = *(const float4*)(g_top + ((size_t)n * NPRE + i) * 4);
    float ai = (bi.z - bi.x) * (bi.w - bi.y);
    unsigned long long bits = 0;
    int jmax = min(64, NPRE - jt * 64);
#pragma unroll 4
    for (int q = 0; q < 64; q++) {
        if (q < jmax) {
            float4 b2 = sb[q];
            float ty0 = fmaxf(bi.x, b2.x), tx0 = fmaxf(bi.y, b2.y);
            float by0 = fminf(bi.z, b2.z), bx0 = fminf(bi.w, b2.w);
            float ih = fmaxf(by0 - ty0, 0.f), iw = fmaxf(bx0 - tx0, 0.f);
            float inter = ih * iw;
            float iou = inter / (ai + sarea[q] - inter + 1e-9f);
            if (iou > 0.7f) bits |= (1ull << q);
        }
    }
    g_mask[((size_t)n * NPRE + i) * NWORDS + jt] = bits;
}

// ---------------- K5: sequential suppression + ROI writeout ----------------
__global__ void __launch_bounds__(128) k_nms(float* __restrict__ out) {
    int n = blockIdx.x;
    int tid = threadIdx.x;
    __shared__ int s_keep[NPOST];
    __shared__ int s_cnt;
    if (tid == 0) s_cnt = 0;
    __syncthreads();
    if (tid < 32) {
        unsigned long long remv[3] = {0, 0, 0};
        int lane = tid;
        int cnt = 0;
        const unsigned long long* mbase = g_mask + (size_t)n * NPRE * NWORDS;
        for (int i = 0; i < NPRE && cnt < NPOST; i++) {
            int w = i >> 6, b2 = i & 63;
            int owner = w & 31, slot = w >> 5;
            unsigned long long wordv = (slot == 0) ? remv[0] : ((slot == 1) ? remv[1] : remv[2]);
            int rm = (int)((wordv >> b2) & 1ull);
            rm = __shfl_sync(0xffffffffu, rm, owner);
            if (!rm) {
                if (lane == 0) s_keep[cnt] = i;
                cnt++;
                const unsigned long long* row = mbase + (size_t)i * NWORDS;
                if (lane < NWORDS) remv[0] |= row[lane];
                if (lane + 32 < NWORDS) remv[1] |= row[lane + 32];
                if (lane + 64 < NWORDS) remv[2] |= row[lane + 64];
            }
        }
        if (lane == 0) s_cnt = cnt;
    }
    __syncthreads();
    int cnt = s_cnt;
    if (tid == 0 && cnt < NPOST) {
        // reference argsort-padding: suppressed indices ascending
        int ptr = 0, fill = cnt;
        for (int i = 0; i < NPRE && fill < NPOST; i++) {
            if (ptr < cnt && s_keep[ptr] == i) ptr++;
            else s_keep[fill++] = i;
        }
    }
    __syncthreads();
    for (int r2 = tid; r2 < NPOST; r2 += 128) {
        int idx = s_keep[r2];
        float4 bb = *(const float4*)(g_top + ((size_t)n * NPRE + idx) * 4);
        float* o = out + OFF_ROIS + ((size_t)n * NPOST + r2) * 4;
        o[0] = bb.x; o[1] = bb.y; o[2] = bb.z; o[3] = bb.w;
        out[OFF_RIDX + n * NPOST + r2] = (float)n;
    }
}

// ---------------- launch ----------------
extern "C" void kernel_launch(void* const* d_in, const int* in_sizes, int n_in,
                              void* d_out, int out_size) {
    const float* x  = (const float*)d_in[0];
    const float* w1 = (const float*)d_in[1];
    const float* b1 = (const float*)d_in[2];
    const float* sw = (const float*)d_in[3];
    const float* sb = (const float*)d_in[4];
    const float* lw = (const float*)d_in[5];
    const float* lb = (const float*)d_in[6];
    const void* pih = d_in[7];
    const void* piw = d_in[8];
    float* out = (float*)d_out;

    k_wt<<<256, 256>>>(w1);
    k_conv<<<dim3(256, 2), 256>>>(x, b1);
    k_heads<<<8192, 256>>>(lw, lb, sw, sb, out, pih, piw);
    cudaFuncSetAttribute(k_topk, cudaFuncAttributeMaxDynamicSharedMemorySize, 213504);
    k_topk<<<8, 1024, 212992>>>();
    k_mask<<<dim3(94, 94, 8), 64>>>();
    k_nms<<<8, 128>>>(out);
}

// round 2
// speedup vs baseline: 1.1163x; 1.1163x over previous
#include <cuda_runtime.h>
#include <math.h>
#include <stdint.h>

#define NIMG 8
#define CIN 256
#define HW 4096
#define NA 9
#define APIMG 36864      // HW * NA
#define NPRE 6000
#define NPOST 300
#define KDIM 2304        // 256 * 9
#define NWORDS 94        // ceil(6000/64)
#define KSTEPS 288       // KDIM/8

#define OFF_LOC   0
#define OFF_SCORE 1179648
#define OFF_ROIS  1769472
#define OFF_RIDX  1779072
#define OFF_ANCH  1781472

// ---------------- static device scratch ----------------
__device__ float g_wT[KDIM * 256];
__device__ float g_h[NIMG * CIN * HW];
__device__ float g_boxes[NIMG * APIMG * 4];
__device__ unsigned g_key[NIMG * APIMG];
__device__ float g_top[NIMG * NPRE * 4];
__device__ unsigned long long g_mask[(size_t)NIMG * NPRE * NWORDS];

__device__ __forceinline__ float read_dim(const void* p) {
    int v = *(const int*)p;
    if (v > 0 && v < 1048576) return (float)v;
    long long l = *(const long long*)p;
    if (l > 0 && l < 1048576) return (float)l;
    return *(const float*)p;
}

// ---------------- K0: transpose conv1 weights to k-major (k = tap*256 + c) ----------------
__global__ void k_wt(const float* __restrict__ w) {
    int o = blockIdx.x;
    for (int k = threadIdx.x; k < KDIM; k += 256) {
        int c = k & 255;
        int tap = k >> 8;
        g_wT[(size_t)k * 256 + o] = w[(size_t)o * KDIM + c * 9 + tap];
    }
}

// ---------------- K1: conv3x3 SAME + bias + relu, implicit im2col SGEMM ----------------
// 128x128x8 tiles, double-buffered smem, register prefetch.
// M = 32768 pixels, N = 256 out channels, K = 2304 (tap-major: k = tap*256 + c).
__global__ void __launch_bounds__(256, 2) k_conv(const float* __restrict__ x,
                                                 const float* __restrict__ bias) {
    __shared__ __align__(16) float As[2][8][128];
    __shared__ __align__(16) float Bs[2][8][128];
    const int m0 = blockIdx.x * 128;
    const int n0 = blockIdx.y * 128;
    const int tid = threadIdx.x;
    const int tx = tid & 15, ty = tid >> 4;

    // Per-thread load geometry: l = (tid + t*256) & 127 = tid & 127 (invariant),
    // kk = (tid>>7) + 2t. Pixel geometry hoisted out of the K loop.
    const int ll = tid & 127;
    const int kb = tid >> 7;                 // 0 or 1
    const int m = m0 + ll;
    const int nimg = m >> 12;
    const int p = m & 4095;
    const int yy = p >> 6, xx = p & 63;
    const float* xb = x + (((size_t)nimg * CIN) << 12);
    const float* wb = g_wT + (size_t)kb * 256 + n0 + ll;

    float acc[8][8];
#pragma unroll
    for (int i = 0; i < 8; i++)
#pragma unroll
        for (int j = 0; j < 8; j++) acc[i][j] = 0.f;

    float va[4], vb[4];

#define LOADT(k0_)                                                              \
    {                                                                           \
        const int k0 = (k0_);                                                   \
        const int tap = k0 >> 8;                                                \
        const int ky = tap / 3;                                                 \
        const int kx = tap - ky * 3;                                            \
        const int y2 = yy + ky - 1, x2 = xx + kx - 1;                           \
        const bool inb = ((unsigned)y2 < 64u) && ((unsigned)x2 < 64u);          \
        const int aoff = (((k0 & 255) + kb) << 12) + (y2 << 6) + x2;            \
        const float* bp = wb + (size_t)k0 * 256;                                \
        _Pragma("unroll")                                                       \
        for (int t = 0; t < 4; t++) {                                           \
            va[t] = inb ? __ldg(xb + aoff + (t << 13)) : 0.f;                   \
            vb[t] = __ldg(bp + (size_t)t * 512);                                \
        }                                                                       \
    }

#define STORET(buf_)                                                            \
    {                                                                           \
        const int bf = (buf_);                                                  \
        _Pragma("unroll")                                                       \
        for (int t = 0; t < 4; t++) {                                           \
            As[bf][kb + 2 * t][ll] = va[t];                                     \
            Bs[bf][kb + 2 * t][ll] = vb[t];                                     \
        }                                                                       \
    }

    LOADT(0);
    STORET(0);
    __syncthreads();

    for (int s = 0; s < KSTEPS; s++) {
        const int cur = s & 1;
        if (s + 1 < KSTEPS) LOADT((s + 1) * 8);
#pragma unroll
        for (int kk = 0; kk < 8; kk++) {
            float4 a0 = ((const float4*)As[cur][kk])[ty * 2];
            float4 a1 = ((const float4*)As[cur][kk])[ty * 2 + 1];
            float4 b0 = ((const float4*)Bs[cur][kk])[tx * 2];
            float4 b1 = ((const float4*)Bs[cur][kk])[tx * 2 + 1];
            float av[8] = {a0.x, a0.y, a0.z, a0.w, a1.x, a1.y, a1.z, a1.w};
            float bv[8] = {b0.x, b0.y, b0.z, b0.w, b1.x, b1.y, b1.z, b1.w};
#pragma unroll
            for (int i2 = 0; i2 < 8; i2++)
#pragma unroll
                for (int j2 = 0; j2 < 8; j2++) acc[i2][j2] += av[i2] * bv[j2];
        }
        if (s + 1 < KSTEPS) STORET((s + 1) & 1);
        __syncthreads();
    }
#undef LOADT
#undef STORET

#pragma unroll
    for (int i = 0; i < 8; i++) {
        int mo = m0 + ty * 8 + i;
        int n = mo >> 12;
        int pp = mo & 4095;
#pragma unroll
        for (int j = 0; j < 8; j++) {
            int o = n0 + tx * 8 + j;
            g_h[(((size_t)n * CIN + o) << 12) + pp] = fmaxf(acc[i][j] + bias[o], 0.f);
        }
    }
}

// ---------------- K2: fused 1x1 heads + softmax-fg + decode/clip/valid + keys ----------------
__global__ void __launch_bounds__(256) k_heads(const float* __restrict__ lw,
                                               const float* __restrict__ lb,
                                               const float* __restrict__ sw,
                                               const float* __restrict__ sb,
                                               float* __restrict__ out,
                                               const void* pih, const void* piw) {
    __shared__ float sh[4][256];
    __shared__ float so[4][56];
    int p0 = blockIdx.x * 4;
    int n = p0 >> 12;
    int pbase = p0 & 4095;
    for (int idx = threadIdx.x; idx < 1024; idx += 256) {
        int px = idx & 3;
        int c = idx >> 2;
        sh[px][c] = g_h[(((size_t)n * CIN + c) << 12) + pbase + px];
    }
    __syncthreads();
    {
        int px = threadIdx.x >> 6;
        int ch = threadIdx.x & 63;
        if (ch < 54) {
            const float* wv;
            float bv;
            if (ch < 36) { wv = lw + (size_t)ch * 256; bv = lb[ch]; }
            else         { wv = sw + (size_t)(ch - 36) * 256; bv = sb[ch - 36]; }
            float acc = 0.f;
#pragma unroll 8
            for (int k = 0; k < 256; k++) acc += sh[px][k] * wv[k];
            acc += bv;
            so[px][ch] = acc;
            int pp = (p0 + px) & 4095;
            if (ch < 36)
                out[OFF_LOC + (size_t)n * 147456 + (size_t)pp * 36 + ch] = acc;
            else
                out[OFF_SCORE + (size_t)n * 73728 + (size_t)pp * 18 + (ch - 36)] = acc;
        }
    }
    __syncthreads();
    if (threadIdx.x < 36) {
        int px = threadIdx.x / 9;
        int a = threadIdx.x % 9;
        int pp = (p0 + px) & 4095;
        int y = pp >> 6, xq = pp & 63;
        const double RAT[3] = {0.5, 1.0, 2.0};
        const double SCL[3] = {8.0, 16.0, 32.0};
        int ri = a / 3, sj = a % 3;
        double hh = 7.0 * SCL[sj] * sqrt(RAT[ri]);
        double wd = 7.0 * SCL[sj] * sqrt(1.0 / RAT[ri]);
        float ab0 = (float)(3.5 - hh / 2.0), ab1 = (float)(3.5 - wd / 2.0);
        float ab2 = (float)(3.5 + hh / 2.0), ab3 = (float)(3.5 + wd / 2.0);
        float shy = (float)(y * 16), shx = (float)(xq * 16);
        float A0 = shy + ab0, A1 = shx + ab1, A2 = shy + ab2, A3 = shx + ab3;
        long aidx = (long)pp * NA + a;
        if (n == 0) {
            float* ao = out + OFF_ANCH + (size_t)aidx * 4;
            ao[0] = A0; ao[1] = A1; ao[2] = A2; ao[3] = A3;
        }
        float ah = A2 - A0, aw = A3 - A1;
        float acy = A0 + 0.5f * ah, acx = A1 + 0.5f * aw;
        float dy = so[px][a * 4 + 0], dx = so[px][a * 4 + 1];
        float dh = so[px][a * 4 + 2], dw = so[px][a * 4 + 3];
        float cy = dy * ah + acy;
        float cx = dx * aw + acx;
        float bh = expf(dh) * ah;
        float bw = expf(dw) * aw;
        float imh = read_dim(pih), imw = read_dim(piw);
        float y1 = fminf(fmaxf(cy - 0.5f * bh, 0.f), imh);
        float x1 = fminf(fmaxf(cx - 0.5f * bw, 0.f), imw);
        float y2 = fminf(fmaxf(cy + 0.5f * bh, 0.f), imh);
        float x2 = fminf(fmaxf(cx + 0.5f * bw, 0.f), imw);
        bool valid = ((y2 - y1) >= 16.f) && ((x2 - x1) >= 16.f);
        float s0 = so[px][36 + 2 * a], s1 = so[px][37 + 2 * a];
        float mm = fmaxf(s0, s1);
        float e0 = expf(s0 - mm), e1 = expf(s1 - mm);
        float fg = __fdiv_rn(e1, __fadd_rn(e0, e1));
        float sc = valid ? fg : -INFINITY;
        unsigned u = __float_as_uint(sc);
        unsigned sbits = (u & 0x80000000u) ? ~u : (u | 0x80000000u);
        size_t gi = (size_t)n * APIMG + aidx;
        g_key[gi] = ~sbits;
        float* bp = g_boxes + gi * 4;
        bp[0] = y1; bp[1] = x1; bp[2] = y2; bp[3] = x2;
    }
}

// ---------------- K3: exact top-6000 per image (radix select + bitonic sort) ----------------
__global__ void __launch_bounds__(1024) k_topk() {
    extern __shared__ unsigned smem[];
    unsigned* keys = smem;
    unsigned long long* buf = (unsigned long long*)(smem + APIMG);
    __shared__ int hist[256];
    __shared__ unsigned s_val;
    __shared__ int s_rem;
    __shared__ int s_cnt;
    int n = blockIdx.x;
    int tid = threadIdx.x;
    const unsigned* gk = g_key + (size_t)n * APIMG;
    for (int i = tid; i < APIMG; i += 1024) keys[i] = gk[i];
    __syncthreads();

    unsigned prefix = 0, mask = 0;
    int rem = NPRE;
    for (int pass = 0; pass < 4; pass++) {
        int shift = 24 - pass * 8;
        if (tid < 256) hist[tid] = 0;
        __syncthreads();
        for (int i = tid; i < APIMG; i += 1024) {
            unsigned k = keys[i];
            if ((k & mask) == prefix) atomicAdd(&hist[(k >> shift) & 255], 1);
        }
        __syncthreads();
        if (tid == 0) {
            int accu = 0;
            for (int d = 0; d < 256; d++) {
                int c = hist[d];
                if (accu + c >= rem) { s_val = prefix | ((unsigned)d << shift); s_rem = rem - accu; break; }
                accu += c;
            }
        }
        __syncthreads();
        prefix = s_val;
        rem = s_rem;
        mask |= (0xFFu << shift);
    }
    unsigned T = prefix;
    int r = rem;

    unsigned ipref = 0, im = 0;
    int ir = r;
    for (int pass = 0; pass < 2; pass++) {
        int shift = 8 - pass * 8;
        if (tid < 256) hist[tid] = 0;
        __syncthreads();
        for (int i = tid; i < APIMG; i += 1024) {
            if (keys[i] == T && (((unsigned)i & im) == ipref))
                atomicAdd(&hist[((unsigned)i >> shift) & 255], 1);
        }
        __syncthreads();
        if (tid == 0) {
            int accu = 0;
            for (int d = 0; d < 256; d++) {
                int c = hist[d];
                if (accu + c >= ir) { s_val = ipref | ((unsigned)d << shift); s_rem = ir - accu; break; }
                accu += c;
            }
        }
        __syncthreads();
        ipref = s_val;
        ir = s_rem;
        im |= (0xFFu << shift);
    }
    unsigned idxT = ipref;

    if (tid == 0) s_cnt = 0;
    __syncthreads();
    for (int i = tid; i < APIMG; i += 1024) {
        unsigned k = keys[i];
        if (k < T || (k == T && (unsigned)i <= idxT)) {
            int pos = atomicAdd(&s_cnt, 1);
            buf[pos] = (((unsigned long long)k) << 32) | (unsigned)i;
        }
    }
    __syncthreads();
    int cnt = s_cnt;
    for (int i = tid; i < 8192; i += 1024)
        if (i >= cnt) buf[i] = 0xFFFFFFFFFFFFFFFFull;
    __syncthreads();
    for (int size = 2; size <= 8192; size <<= 1) {
        for (int stride = size >> 1; stride > 0; stride >>= 1) {
            for (int i = tid; i < 8192; i += 1024) {
                int ixj = i ^ stride;
                if (ixj > i) {
                    bool up = ((i & size) == 0);
                    unsigned long long vaa = buf[i], vbb = buf[ixj];
                    if ((vaa > vbb) == up) { buf[i] = vbb; buf[ixj] = vaa; }
                }
            }
            __syncthreads();
        }
    }
    for (int r2 = tid; r2 < NPRE; r2 += 1024) {
        unsigned idx = (unsigned)(buf[r2] & 0xFFFFFFFFull);
        float4 bb = *(const float4*)(g_boxes + ((size_t)n * APIMG + idx) * 4);
        *(float4*)(g_top + ((size_t)n * NPRE + r2) * 4) = bb;
    }
}

// ---------------- K4: NMS bitmask matrix (upper triangle only) ----------------
__global__ void __launch_bounds__(64) k_mask() {
    int n = blockIdx.z;
    int it = blockIdx.x, jt = blockIdx.y;
    if (jt < it) return;   // lower triangle never consumed (scan ORs words >= i>>6 only)
    __shared__ float4 sb[64];
    __shared__ float sarea[64];
    int tid = threadIdx.x;
    int j = jt * 64 + tid;
    float4 bj = (j < NPRE) ? *(const float4*)(g_top + ((size_t)n * NPRE + j) * 4)
                           : make_float4(0, 0, 0, 0);
    sb[tid] = bj;
    sarea[tid] = (bj.z - bj.x) * (bj.w - bj.y);
    __syncthreads();
    int i = it * 64 + tid;
    if (i >= NPRE) return;
    float4 bi = *(const float4*)(g_top + ((size_t)n * NPRE + i) * 4);
    float ai = (bi.z - bi.x) * (bi.w - bi.y);
    unsigned long long bits = 0;
    int jmax = min(64, NPRE - jt * 64);
#pragma unroll 4
    for (int q = 0; q < 64; q++) {
        if (q < jmax) {
            float4 b2 = sb[q];
            float ty0 = fmaxf(bi.x, b2.x), tx0 = fmaxf(bi.y, b2.y);
            float by0 = fminf(bi.z, b2.z), bx0 = fminf(bi.w, b2.w);
            float ih = fmaxf(by0 - ty0, 0.f), iw = fmaxf(bx0 - tx0, 0.f);
            float inter = ih * iw;
            float iou = inter / (ai + sarea[q] - inter + 1e-9f);
            if (iou > 0.7f) bits |= (1ull << q);
        }
    }
    g_mask[((size_t)n * NPRE + i) * NWORDS + jt] = bits;
}

// ---------------- K5: sequential suppression + ROI writeout ----------------
__global__ void __launch_bounds__(32) k_nms(float* __restrict__ out) {
    int n = blockIdx.x;
    int lane = threadIdx.x;
    __shared__ int s_keep[NPOST];
    __shared__ int s_cnt;
    unsigned long long remv0 = 0, remv1 = 0, remv2 = 0;
    int cnt = 0;
    const unsigned long long* mbase = g_mask + (size_t)n * NPRE * NWORDS;
    for (int w = 0; w < NWORDS && cnt < NPOST; w++) {
        int owner = w & 31, slot = w >> 5;
        unsigned long long myv = (slot == 0) ? remv0 : ((slot == 1) ? remv1 : remv2);
        unsigned long long cur = __shfl_sync(0xffffffffu, myv, owner);
        int bmax = min(64, NPRE - (w << 6));
        for (int b = 0; b < bmax; b++) {
            if (!((cur >> b) & 1ull)) {
                int i = (w << 6) + b;
                if (lane == 0) s_keep[cnt] = i;
                cnt++;
                const unsigned long long* row = mbase + (size_t)i * NWORDS;
                if (lane >= w && lane < NWORDS) remv0 |= __ldg(row + lane);
                if (lane + 32 >= w && lane + 32 < NWORDS) remv1 |= __ldg(row + lane + 32);
                if (lane + 64 >= w && lane + 64 < NWORDS) remv2 |= __ldg(row + lane + 64);
                if (cnt >= NPOST) break;
                myv = (slot == 0) ? remv0 : ((slot == 1) ? remv1 : remv2);
                cur |= __shfl_sync(0xffffffffu, myv, owner);
            }
        }
    }
    if (lane == 0) s_cnt = cnt;
    __syncwarp();
    if (lane == 0 && cnt < NPOST) {
        int ptr = 0, fill = cnt;
        for (int i = 0; i < NPRE && fill < NPOST; i++) {
            if (ptr < cnt && s_keep[ptr] == i) ptr++;
            else s_keep[fill++] = i;
        }
    }
    __syncwarp();
    for (int r2 = lane; r2 < NPOST; r2 += 32) {
        int idx = s_keep[r2];
        float4 bb = *(const float4*)(g_top + ((size_t)n * NPRE + idx) * 4);
        float* o = out + OFF_ROIS + ((size_t)n * NPOST + r2) * 4;
        o[0] = bb.x; o[1] = bb.y; o[2] = bb.z; o[3] = bb.w;
        out[OFF_RIDX + n * NPOST + r2] = (float)n;
    }
}

// ---------------- launch ----------------
extern "C" void kernel_launch(void* const* d_in, const int* in_sizes, int n_in,
                              void* d_out, int out_size) {
    const float* x  = (const float*)d_in[0];
    const float* w1 = (const float*)d_in[1];
    const float* b1 = (const float*)d_in[2];
    const float* sw = (const float*)d_in[3];
    const float* sb = (const float*)d_in[4];
    const float* lw = (const float*)d_in[5];
    const float* lb = (const float*)d_in[6];
    const void* pih = d_in[7];
    const void* piw = d_in[8];
    float* out = (float*)d_out;

    k_wt<<<256, 256>>>(w1);
    k_conv<<<dim3(256, 2), 256>>>(x, b1);
    k_heads<<<8192, 256>>>(lw, lb, sw, sb, out, pih, piw);
    cudaFuncSetAttribute(k_topk, cudaFuncAttributeMaxDynamicSharedMemorySize, 213504);
    k_topk<<<8, 1024, 212992>>>();
    k_mask<<<dim3(94, 94, 8), 64>>>();
    k_nms<<<8, 32>>>(out);
}